// round 11
// baseline (speedup 1.0000x reference)
#include <cuda_runtime.h>
#include <cstdint>

namespace {

constexpr int B_ = 32768, A_ = 32, D_ = 64, H_ = 128, K_ = 128;
constexpr int NCH = 256;     // 128-row chunks (khctx)
constexpr int ZCH = 512;     // 64-row chunks (kz)
constexpr int GRP = 8;       // action groups of 4

using u64 = unsigned long long;

// khctx smem
constexpr int CTXS   = 132;          // padded ctx row stride (floats)
constexpr int OFF_CTX = 0;           // 128*132 = 16896 f
constexpr int OFF_WZ0 = 16896;       // u64[64][128] = 16384 f
constexpr int HSMEM   = (16896 + 16384) * 4;  // 133120 B

// kz smem (floats)
constexpr int ZF_CTX = 0;            // 64*132 = 8448 f
constexpr int ZF_WZ  = 8448;         // u64[8192] = 16384 f
constexpr int ZF_RED = 24832;        // 256 f
constexpr int ZSMEM  = 25088 * 4;    // 100352 B  (fits 2 blocks/SM)

__device__ __forceinline__ void ffma2(u64& d, u64 a, u64 b) {
  asm("fma.rn.f32x2 %0, %1, %2, %0;" : "+l"(d) : "l"(a), "l"(b));
}
__device__ __forceinline__ u64 pack2(float a, float b) {
  u64 r; asm("mov.b64 %0, {%1, %2};" : "=l"(r) : "f"(a), "f"(b)); return r;
}
__device__ __forceinline__ void unpack2(u64 v, float& lo, float& hi) {
  asm("mov.b64 {%0, %1}, %2;" : "=f"(lo), "=f"(hi) : "l"(v));
}
__device__ __forceinline__ uint32_t fkey(float f) {
  uint32_t u = __float_as_uint(f);
  return (u & 0x80000000u) ? ~u : (u | 0x80000000u);
}
__device__ __forceinline__ uint32_t smem_u32(const void* p) {
  uint32_t a;
  asm("{ .reg .u64 t; cvta.to.shared.u64 t, %1; cvt.u32.u64 %0, t; }" : "=r"(a) : "l"(p));
  return a;
}
__device__ __forceinline__ void cp16(uint32_t dst, const void* src) {
  asm volatile("cp.async.cg.shared.global [%0], [%1], 16;" :: "r"(dst), "l"(src));
}
__device__ __forceinline__ void cp_commit() {
  asm volatile("cp.async.commit_group;" ::: "memory");
}
__device__ __forceinline__ void cp_wait0() {
  asm volatile("cp.async.wait_group 0;" ::: "memory");
}

}  // namespace

// -------- device scratch (no runtime alloc) --------
__device__ float g_weff[A_ * K_ * D_];                 // [a][k][d]
__device__ float g_beff[A_ * D_];                      // [a][d]
__device__ __align__(16) u64 g_wz[33 * 64 * H_];       // [t][kp][h]; t=32 is Wc
__device__ float g_c2[33 * H_];                        // [t][h]; t=32 is br1
__device__ __align__(16) float g_ctxp[(size_t)B_ * K_];
__device__ float g_hctx[(size_t)B_ * H_];
__device__ u64   g_best[B_];
__device__ int   g_bcnt[A_];
__device__ int   g_bucket[A_ * B_];

// ---------------------------------------------------------------------------
// khctx-style GEMM pass (32x32 warp tile) — used only by khctx
// ---------------------------------------------------------------------------
__device__ __forceinline__ void gemm_pass32(const float* __restrict__ ctxs,
                                            const u64* __restrict__ wzs,
                                            int R0, int Cb, int rg, int cg,
                                            u64 acc[4][4][2]) {
#pragma unroll
  for (int i = 0; i < 4; i++)
#pragma unroll
    for (int j = 0; j < 4; j++) { acc[i][j][0] = 0ull; acc[i][j][1] = 0ull; }

  const float* xb = ctxs + (R0 + rg) * CTXS;
  const u64*   wb = wzs + Cb + 2 * cg;

#pragma unroll 8
  for (int kq = 0; kq < 32; kq++) {
    ulonglong2 xv[4];
#pragma unroll
    for (int i = 0; i < 4; i++)
      xv[i] = *reinterpret_cast<const ulonglong2*>(xb + i * 8 * CTXS + kq * 4);
    ulonglong2 w0[4], w1[4];
#pragma unroll
    for (int j = 0; j < 4; j++) {
      w0[j] = *reinterpret_cast<const ulonglong2*>(wb + (2 * kq + 0) * H_ + 8 * j);
      w1[j] = *reinterpret_cast<const ulonglong2*>(wb + (2 * kq + 1) * H_ + 8 * j);
    }
#pragma unroll
    for (int i = 0; i < 4; i++)
#pragma unroll
      for (int j = 0; j < 4; j++) {
        ffma2(acc[i][j][0], xv[i].x, w0[j].x);
        ffma2(acc[i][j][1], xv[i].x, w0[j].y);
        ffma2(acc[i][j][0], xv[i].y, w1[j].x);
        ffma2(acc[i][j][1], xv[i].y, w1[j].y);
      }
  }
}

// ---------------------------------------------------------------------------
// K1a: Weff[a][k][d] = sum_h W2[a][d][h]*W1[a][h][k];  beff; bcnt reset
// ---------------------------------------------------------------------------
__global__ void __launch_bounds__(256)
k1a_weff(const float* __restrict__ W1, const float* __restrict__ b1,
         const float* __restrict__ W2, const float* __restrict__ b2) {
  __shared__ float w1s[H_][K_];
  __shared__ float w2s[D_][H_];
  const int a = blockIdx.x, tid = threadIdx.x;
  if (a == 0 && tid < A_) g_bcnt[tid] = 0;
  const float* W1a = W1 + (size_t)a * H_ * K_;
  const float* W2a = W2 + (size_t)a * D_ * H_;
  for (int i = tid; i < H_ * K_ / 4; i += 256)
    reinterpret_cast<float4*>(&w1s[0][0])[i] = reinterpret_cast<const float4*>(W1a)[i];
  for (int i = tid; i < D_ * H_ / 4; i += 256)
    reinterpret_cast<float4*>(&w2s[0][0])[i] = reinterpret_cast<const float4*>(W2a)[i];
  __syncthreads();

  const int k0 = (tid & 31) * 4, d0 = (tid >> 5) * 8;
  float acc[4][8];
#pragma unroll
  for (int i = 0; i < 4; i++)
#pragma unroll
    for (int j = 0; j < 8; j++) acc[i][j] = 0.f;
  for (int h = 0; h < H_; h++) {
    float4 w1v = *reinterpret_cast<const float4*>(&w1s[h][k0]);
    float w1x[4] = {w1v.x, w1v.y, w1v.z, w1v.w};
#pragma unroll
    for (int j = 0; j < 8; j++) {
      float w2v = w2s[d0 + j][h];
#pragma unroll
      for (int i = 0; i < 4; i++) acc[i][j] = fmaf(w2v, w1x[i], acc[i][j]);
    }
  }
  float* dst = g_weff + (size_t)a * K_ * D_;
#pragma unroll
  for (int i = 0; i < 4; i++)
#pragma unroll
    for (int j = 0; j < 8; j++) dst[(k0 + i) * D_ + d0 + j] = acc[i][j];

  if (tid < D_) {
    float s = b2[a * D_ + tid];
    for (int h = 0; h < H_; h++) s = fmaf(w2s[tid][h], b1[a * H_ + h], s);
    g_beff[a * D_ + tid] = s;
  }
}

// ---------------------------------------------------------------------------
// K1b: tiles t<32: Wz[t][kp][h] (packed along k); c2[t][h].  Tile 32: Wc+br1.
// ---------------------------------------------------------------------------
__global__ void __launch_bounds__(256)
k1b_wz(const float* __restrict__ Wr1, const float* __restrict__ br1) {
  const int t = blockIdx.x, tid = threadIdx.x;

  if (t == 32) {
    for (int it = 0; it < 32; it++) {
      int idx = tid + it * 256;
      int kp = idx >> 7, h = idx & 127;
      float2 v = *reinterpret_cast<const float2*>(&Wr1[h * 192 + 2 * kp]);
      g_wz[(size_t)32 * 8192 + kp * H_ + h] = pack2(v.x, v.y);
    }
    if (tid < H_) g_c2[32 * H_ + tid] = br1[tid];
    return;
  }

  __shared__ float weffs[K_ * D_];
  __shared__ float wps[H_ * 65];
  for (int i = tid; i < K_ * D_ / 4; i += 256)
    reinterpret_cast<float4*>(weffs)[i] =
        reinterpret_cast<const float4*>(g_weff + (size_t)t * K_ * D_)[i];
  for (int i = tid; i < H_ * D_ / 4; i += 256) {
    int n = i >> 4, q = i & 15;
    float4 v = *reinterpret_cast<const float4*>(&Wr1[n * 192 + 128 + q * 4]);
    wps[n * 65 + q * 4 + 0] = v.x;
    wps[n * 65 + q * 4 + 1] = v.y;
    wps[n * 65 + q * 4 + 2] = v.z;
    wps[n * 65 + q * 4 + 3] = v.w;
  }
  __syncthreads();

  const int h = tid & 127, khalf = tid >> 7;
  float prev = 0.f;
  for (int k = khalf * 64; k < khalf * 64 + 64; k++) {
    float s = 0.f;
#pragma unroll 8
    for (int d = 0; d < D_; d++) s = fmaf(weffs[k * D_ + d], wps[h * 65 + d], s);
    if (k & 1)
      g_wz[(size_t)t * 8192 + (k >> 1) * H_ + h] = pack2(prev, s);
    else
      prev = s;
  }
  if (tid < H_) {
    float s = 0.f;
    for (int d = 0; d < D_; d++) s = fmaf(g_beff[t * D_ + d], wps[tid * 65 + d], s);
    g_c2[t * H_ + tid] = s;
  }
}

// ---------------------------------------------------------------------------
// Khctx: hctx = ctx @ Wc + br1 -> gmem; ctx gather -> g_ctxp; wemb; g_best.
// ---------------------------------------------------------------------------
__global__ void __launch_bounds__(256, 1)
khctx(const int* __restrict__ x, const int* __restrict__ y,
      const float* __restrict__ cemb, const float* __restrict__ wemb,
      float* __restrict__ out) {
  extern __shared__ float smf[];
  const uint32_t smb = smem_u32(smf);
  const int tid = threadIdx.x;
  const int row0 = blockIdx.x * 128;
  const int wid = tid >> 5, lane = tid & 31;
  const int R0 = (wid >> 1) * 32, C0 = (wid & 1) * 32;
  const int rg = lane >> 2, cg = lane & 3;

  {
    int row = tid >> 1, half = tid & 1;
    int gb = row0 + row;
    int xi = x[gb * 2 + half];
    const float4* s4 = reinterpret_cast<const float4*>(cemb + (size_t)xi * 64);
#pragma unroll
    for (int q = 0; q < 16; q++) {
      float4 v = s4[q];
      *reinterpret_cast<float4*>(&smf[OFF_CTX + row * CTXS + half * 64 + q * 4]) = v;
      *reinterpret_cast<float4*>(&g_ctxp[(size_t)gb * K_ + half * 64 + q * 4]) = v;
    }
    int yy = y[gb];
    const float4* w4 = reinterpret_cast<const float4*>(wemb + (size_t)yy * 64 + half * 32);
    float4* o4 = reinterpret_cast<float4*>(&out[(size_t)B_ * 64 + (size_t)gb * 64 + half * 32]);
#pragma unroll
    for (int q = 0; q < 8; q++) o4[q] = w4[q];
  }
  if (tid < 128) g_best[row0 + tid] = ~0ull;

  {
    const u64* src = g_wz + (size_t)32 * 8192;
    for (int it = 0; it < 16; it++) {
      int idx = tid + it * 256;
      cp16(smb + OFF_WZ0 * 4 + idx * 16, src + idx * 2);
    }
    cp_commit(); cp_wait0();
  }
  __syncthreads();

  const u64* wzs = reinterpret_cast<const u64*>(smf + OFF_WZ0);
#pragma unroll 1
  for (int p = 0; p < 2; p++) {
    const int Cb = p * 64 + C0;
    u64 acc[4][4][2];
    gemm_pass32(smf + OFF_CTX, wzs, R0, Cb, rg, cg, acc);
#pragma unroll
    for (int j = 0; j < 4; j++) {
      float2 cc = *reinterpret_cast<const float2*>(&g_c2[32 * H_ + Cb + 8 * j + 2 * cg]);
#pragma unroll
      for (int i = 0; i < 4; i++) {
        float e0, o0, e1, o1;
        unpack2(acc[i][j][0], e0, o0);
        unpack2(acc[i][j][1], e1, o1);
        size_t rr = (size_t)(row0 + R0 + rg + 8 * i);
        *reinterpret_cast<float2*>(&g_hctx[rr * H_ + Cb + 8 * j + 2 * cg]) =
            make_float2(e0 + o0 + cc.x, e1 + o1 + cc.y);
      }
    }
  }
}

// ---------------------------------------------------------------------------
// Kz: 64-row chunks, 2 blocks/SM.  Thread tile 4 rows x 4 cols; 2 col passes.
// ---------------------------------------------------------------------------
__global__ void __launch_bounds__(256, 2)
kz(const float* __restrict__ Wr2) {
  extern __shared__ float smf[];
  u64* wzs = reinterpret_cast<u64*>(smf + ZF_WZ);
  float* red = smf + ZF_RED;
  const uint32_t smb = smem_u32(smf);
  const int tid = threadIdx.x;
  const int row0 = blockIdx.x * 64;
  const int grp = blockIdx.y;
  const int wid = tid >> 5, lane = tid & 31;
  const int R0 = (wid >> 2) * 32, Cq = (wid & 3) * 16, cqi = wid & 3;
  const int rg = lane >> 2, cg = lane & 3;

  float2 wr2v[2][2];
#pragma unroll
  for (int p = 0; p < 2; p++)
#pragma unroll
    for (int j = 0; j < 2; j++)
      wr2v[p][j] = *reinterpret_cast<const float2*>(&Wr2[p * 64 + Cq + 8 * j + 2 * cg]);

  // stage ctx + wz(a0)
  {
    const float* src = g_ctxp + (size_t)row0 * K_;
    for (int it = 0; it < 8; it++) {
      int idx = tid + it * 256;
      int row = idx >> 5, q = idx & 31;
      cp16(smb + (ZF_CTX + row * CTXS + q * 4) * 4, src + row * K_ + q * 4);
    }
    const u64* wsrc = g_wz + (size_t)(grp * 4) * 8192;
    for (int it = 0; it < 16; it++) {
      int idx = tid + it * 256;
      cp16(smb + ZF_WZ * 4 + idx * 16, wsrc + idx * 2);
    }
    cp_commit(); cp_wait0();
  }
  __syncthreads();

#pragma unroll 1
  for (int ai = 0; ai < 4; ai++) {
    const int a = grp * 4 + ai;
    float s[4] = {0.f, 0.f, 0.f, 0.f};

#pragma unroll 1
    for (int p = 0; p < 2; p++) {
      const int Cb = p * 64 + Cq;
      // prefetch epilogue operands (hidden under GEMM)
      float2 cc[2], hc[4][2];
#pragma unroll
      for (int j = 0; j < 2; j++)
        cc[j] = *reinterpret_cast<const float2*>(&g_c2[a * H_ + Cb + 8 * j + 2 * cg]);
#pragma unroll
      for (int i = 0; i < 4; i++)
#pragma unroll
        for (int j = 0; j < 2; j++)
          hc[i][j] = *reinterpret_cast<const float2*>(
              &g_hctx[(size_t)(row0 + R0 + rg + 8 * i) * H_ + Cb + 8 * j + 2 * cg]);

      u64 acc[4][2][2];
#pragma unroll
      for (int i = 0; i < 4; i++)
#pragma unroll
        for (int j = 0; j < 2; j++) { acc[i][j][0] = 0ull; acc[i][j][1] = 0ull; }

      const float* xb = smf + ZF_CTX + (R0 + rg) * CTXS;
      const u64*   wb = wzs + Cb + 2 * cg;
#pragma unroll 8
      for (int kq = 0; kq < 32; kq++) {
        ulonglong2 xv[4];
#pragma unroll
        for (int i = 0; i < 4; i++)
          xv[i] = *reinterpret_cast<const ulonglong2*>(xb + i * 8 * CTXS + kq * 4);
        ulonglong2 w0[2], w1[2];
#pragma unroll
        for (int j = 0; j < 2; j++) {
          w0[j] = *reinterpret_cast<const ulonglong2*>(wb + (2 * kq + 0) * H_ + 8 * j);
          w1[j] = *reinterpret_cast<const ulonglong2*>(wb + (2 * kq + 1) * H_ + 8 * j);
        }
#pragma unroll
        for (int i = 0; i < 4; i++)
#pragma unroll
          for (int j = 0; j < 2; j++) {
            ffma2(acc[i][j][0], xv[i].x, w0[j].x);
            ffma2(acc[i][j][1], xv[i].x, w0[j].y);
            ffma2(acc[i][j][0], xv[i].y, w1[j].x);
            ffma2(acc[i][j][1], xv[i].y, w1[j].y);
          }
      }

#pragma unroll
      for (int i = 0; i < 4; i++)
#pragma unroll
        for (int j = 0; j < 2; j++) {
          float e0, o0, e1, o1;
          unpack2(acc[i][j][0], e0, o0);
          unpack2(acc[i][j][1], e1, o1);
          float z0 = e0 + o0 + hc[i][j].x + cc[j].x;
          float z1 = e1 + o1 + hc[i][j].y + cc[j].y;
          s[i] = fmaf(fmaxf(z0, 0.f), wr2v[p][j].x, s[i]);
          s[i] = fmaf(fmaxf(z1, 0.f), wr2v[p][j].y, s[i]);
        }
    }

    // reduce over cg lanes
#pragma unroll
    for (int i = 0; i < 4; i++) {
      s[i] += __shfl_xor_sync(0xffffffffu, s[i], 1);
      s[i] += __shfl_xor_sync(0xffffffffu, s[i], 2);
    }
    if (cg == 0) {
#pragma unroll
      for (int i = 0; i < 4; i++)
        red[(R0 + rg + 8 * i) * 4 + cqi] = s[i];
    }
    __syncthreads();   // gemm reads of wz done; red visible

    if (ai < 3) {      // overlap next-wz staging with argmin
      const u64* src = g_wz + (size_t)(a + 1) * 8192;
      for (int it = 0; it < 16; it++) {
        int idx = tid + it * 256;
        cp16(smb + ZF_WZ * 4 + idx * 16, src + idx * 2);
      }
      cp_commit();
    }
    if (tid < 64) {
      float tot = red[tid * 4] + red[tid * 4 + 1] + red[tid * 4 + 2] + red[tid * 4 + 3];
      u64 key = ((u64)fkey(tot) << 32) | (unsigned)a;
      atomicMin(&g_best[row0 + tid], key);   // ties -> smaller a = first-min
    }
    if (ai < 3) cp_wait0();
    __syncthreads();
  }
}

// ---------------------------------------------------------------------------
// K2b: bucket rows by winning action.
// ---------------------------------------------------------------------------
__global__ void __launch_bounds__(256)
k2b_bucket() {
  int b = blockIdx.x * 256 + threadIdx.x;
  if (b < B_) {
    u64 v = g_best[b];
    int a = (int)(v & 0xFFu);
    int slot = atomicAdd(&g_bcnt[a], 1);
    g_bucket[a * B_ + slot] = b;
  }
}

// ---------------------------------------------------------------------------
// K3: winner preds (exact fp32), bucketed by action (64 chunks per action).
// ---------------------------------------------------------------------------
__global__ void __launch_bounds__(256)
k3_preds(const int* __restrict__ x, const float* __restrict__ cemb,
         float* __restrict__ out) {
  __shared__ float weffs[K_ * D_];
  __shared__ float ctxb[8][K_];
  const int a = blockIdx.x >> 6;
  const int chunk = blockIdx.x & 63;
  const int tid = threadIdx.x, wid = tid >> 5, lid = tid & 31;

  for (int i = tid; i < K_ * D_ / 4; i += 256)
    reinterpret_cast<float4*>(weffs)[i] =
        reinterpret_cast<const float4*>(g_weff + (size_t)a * K_ * D_)[i];
  __syncthreads();

  const int cnt = g_bcnt[a];
  const float bf0 = g_beff[a * D_ + 2 * lid];
  const float bf1 = g_beff[a * D_ + 2 * lid + 1];

  for (int ii = wid;; ii += 8) {
    int i = chunk + 64 * ii;
    if (i >= cnt) break;
    int b = g_bucket[a * B_ + i];
    {
      int k0 = lid * 4;
      int xi = x[2 * b + (lid >> 4)];
      float4 v = *reinterpret_cast<const float4*>(cemb + (size_t)xi * 64 + (k0 & 63));
      *reinterpret_cast<float4*>(&ctxb[wid][k0]) = v;
    }
    __syncwarp();
    float s0 = bf0, s1 = bf1;
#pragma unroll 4
    for (int k = 0; k < K_; k++) {
      float c = ctxb[wid][k];
      s0 = fmaf(c, weffs[k * D_ + 2 * lid], s0);
      s1 = fmaf(c, weffs[k * D_ + 2 * lid + 1], s1);
    }
    *reinterpret_cast<float2*>(&out[(size_t)b * 64 + 2 * lid]) = make_float2(s0, s1);
    __syncwarp();
  }
}

extern "C" void kernel_launch(void* const* d_in, const int* in_sizes, int n_in,
                              void* d_out, int out_size) {
  (void)in_sizes; (void)n_in; (void)out_size;
  const int*   x    = (const int*)d_in[0];
  const int*   y    = (const int*)d_in[1];
  const float* cemb = (const float*)d_in[2];
  const float* wemb = (const float*)d_in[3];
  const float* W1   = (const float*)d_in[4];
  const float* b1   = (const float*)d_in[5];
  const float* W2   = (const float*)d_in[6];
  const float* b2   = (const float*)d_in[7];
  const float* Wr1  = (const float*)d_in[8];
  const float* br1  = (const float*)d_in[9];
  const float* Wr2  = (const float*)d_in[10];
  float* out = (float*)d_out;

  cudaFuncSetAttribute(khctx, cudaFuncAttributeMaxDynamicSharedMemorySize, HSMEM);
  cudaFuncSetAttribute(kz, cudaFuncAttributeMaxDynamicSharedMemorySize, ZSMEM);

  k1a_weff<<<A_, 256>>>(W1, b1, W2, b2);
  k1b_wz<<<33, 256>>>(Wr1, br1);
  khctx<<<NCH, 256, HSMEM>>>(x, y, cemb, wemb, out);
  kz<<<dim3(ZCH, GRP), 256, ZSMEM>>>(Wr2);
  k2b_bucket<<<B_ / 256, 256>>>();
  k3_preds<<<A_ * 64, 256>>>(x, cemb, out);
}

// round 13
// speedup vs baseline: 1.0949x; 1.0949x over previous
#include <cuda_runtime.h>
#include <cstdint>

namespace {

constexpr int B_ = 32768, A_ = 32, D_ = 64, H_ = 128, K_ = 128;
constexpr int ZCH = 512;     // 64-row chunks (kz)
constexpr int GRP = 8;       // action groups of 4

using u64 = unsigned long long;

// kz smem (floats)
constexpr int CTXS   = 132;          // padded ctx row stride (floats)
constexpr int ZF_CTX = 0;            // 64*132 = 8448 f
constexpr int ZF_WZ  = 8448;         // u64[8192] = 16384 f
constexpr int ZF_RED = 24832;        // 256 f
constexpr int ZSMEM  = 25088 * 4;    // 100352 B  (2 blocks/SM)

__device__ __forceinline__ void ffma2(u64& d, u64 a, u64 b) {
  asm("fma.rn.f32x2 %0, %1, %2, %0;" : "+l"(d) : "l"(a), "l"(b));
}
__device__ __forceinline__ u64 pack2(float a, float b) {
  u64 r; asm("mov.b64 %0, {%1, %2};" : "=l"(r) : "f"(a), "f"(b)); return r;
}
__device__ __forceinline__ void unpack2(u64 v, float& lo, float& hi) {
  asm("mov.b64 {%0, %1}, %2;" : "=f"(lo), "=f"(hi) : "l"(v));
}
__device__ __forceinline__ uint32_t fkey(float f) {
  uint32_t u = __float_as_uint(f);
  return (u & 0x80000000u) ? ~u : (u | 0x80000000u);
}
__device__ __forceinline__ uint32_t smem_u32(const void* p) {
  uint32_t a;
  asm("{ .reg .u64 t; cvta.to.shared.u64 t, %1; cvt.u32.u64 %0, t; }" : "=r"(a) : "l"(p));
  return a;
}
__device__ __forceinline__ void cp16(uint32_t dst, const void* src) {
  asm volatile("cp.async.cg.shared.global [%0], [%1], 16;" :: "r"(dst), "l"(src));
}
__device__ __forceinline__ void cp_commit() {
  asm volatile("cp.async.commit_group;" ::: "memory");
}
__device__ __forceinline__ void cp_wait0() {
  asm volatile("cp.async.wait_group 0;" ::: "memory");
}

}  // namespace

// -------- device scratch (no runtime alloc) --------
__device__ float g_weff[A_ * K_ * D_];                 // [a][k][d]
__device__ float g_beff[A_ * D_];                      // [a][d]
__device__ __align__(16) u64 g_wz[A_ * 64 * H_];       // [a][kp][h]; Wz+Wc folded
__device__ float g_c2[A_ * H_];                        // [a][h];    c2+br1 folded
__device__ __align__(16) float g_ctxp[(size_t)B_ * K_];
__device__ u64   g_best[B_];
__device__ int   g_bcnt[A_];
__device__ int   g_bucket[A_ * B_];

// ---------------------------------------------------------------------------
// K1a: Weff[a][k][d] = sum_h W2[a][d][h]*W1[a][h][k];  beff; bcnt reset
// ---------------------------------------------------------------------------
__global__ void __launch_bounds__(256)
k1a_weff(const float* __restrict__ W1, const float* __restrict__ b1,
         const float* __restrict__ W2, const float* __restrict__ b2) {
  __shared__ float w1s[H_][K_];
  __shared__ float w2s[D_][H_];
  const int a = blockIdx.x, tid = threadIdx.x;
  if (a == 0 && tid < A_) g_bcnt[tid] = 0;
  const float* W1a = W1 + (size_t)a * H_ * K_;
  const float* W2a = W2 + (size_t)a * D_ * H_;
  for (int i = tid; i < H_ * K_ / 4; i += 256)
    reinterpret_cast<float4*>(&w1s[0][0])[i] = reinterpret_cast<const float4*>(W1a)[i];
  for (int i = tid; i < D_ * H_ / 4; i += 256)
    reinterpret_cast<float4*>(&w2s[0][0])[i] = reinterpret_cast<const float4*>(W2a)[i];
  __syncthreads();

  const int k0 = (tid & 31) * 4, d0 = (tid >> 5) * 8;
  float acc[4][8];
#pragma unroll
  for (int i = 0; i < 4; i++)
#pragma unroll
    for (int j = 0; j < 8; j++) acc[i][j] = 0.f;
  for (int h = 0; h < H_; h++) {
    float4 w1v = *reinterpret_cast<const float4*>(&w1s[h][k0]);
    float w1x[4] = {w1v.x, w1v.y, w1v.z, w1v.w};
#pragma unroll
    for (int j = 0; j < 8; j++) {
      float w2v = w2s[d0 + j][h];
#pragma unroll
      for (int i = 0; i < 4; i++) acc[i][j] = fmaf(w2v, w1x[i], acc[i][j]);
    }
  }
  float* dst = g_weff + (size_t)a * K_ * D_;
#pragma unroll
  for (int i = 0; i < 4; i++)
#pragma unroll
    for (int j = 0; j < 8; j++) dst[(k0 + i) * D_ + d0 + j] = acc[i][j];

  if (tid < D_) {
    float s = b2[a * D_ + tid];
    for (int h = 0; h < H_; h++) s = fmaf(w2s[tid][h], b1[a * H_ + h], s);
    g_beff[a * D_ + tid] = s;
  }
}

// ---------------------------------------------------------------------------
// K1b: Wz'[a][kp][h] = pack over k of ( Wc[h][k] + sum_d Weff[a][k][d]*Wp[h][d] )
//      c2'[a][h]     = br1[h] + sum_d beff[a][d]*Wp[h][d]
// (Wc = Wr1[:, :128], Wp = Wr1[:, 128:192])
// ---------------------------------------------------------------------------
__global__ void __launch_bounds__(256)
k1b_wz(const float* __restrict__ Wr1, const float* __restrict__ br1) {
  __shared__ float weffs[K_ * D_];
  __shared__ float wps[H_ * 65];
  const int a = blockIdx.x, tid = threadIdx.x;

  for (int i = tid; i < K_ * D_ / 4; i += 256)
    reinterpret_cast<float4*>(weffs)[i] =
        reinterpret_cast<const float4*>(g_weff + (size_t)a * K_ * D_)[i];
  for (int i = tid; i < H_ * D_ / 4; i += 256) {
    int n = i >> 4, q = i & 15;
    float4 v = *reinterpret_cast<const float4*>(&Wr1[n * 192 + 128 + q * 4]);
    wps[n * 65 + q * 4 + 0] = v.x;
    wps[n * 65 + q * 4 + 1] = v.y;
    wps[n * 65 + q * 4 + 2] = v.z;
    wps[n * 65 + q * 4 + 3] = v.w;
  }
  __syncthreads();

  const int h = tid & 127, khalf = tid >> 7;
  float prev = 0.f;
  for (int k = khalf * 64; k < khalf * 64 + 64; k++) {
    float s = Wr1[h * 192 + k];          // fold Wc
#pragma unroll 8
    for (int d = 0; d < D_; d++) s = fmaf(weffs[k * D_ + d], wps[h * 65 + d], s);
    if (k & 1)
      g_wz[(size_t)a * 8192 + (k >> 1) * H_ + h] = pack2(prev, s);
    else
      prev = s;
  }
  if (tid < H_) {
    float s = br1[tid];                  // fold br1
    for (int d = 0; d < D_; d++) s = fmaf(g_beff[a * D_ + d], wps[tid * 65 + d], s);
    g_c2[a * H_ + tid] = s;
  }
}

// ---------------------------------------------------------------------------
// Kgather: ctx -> g_ctxp (packed); wemb copy; g_best init.  128 rows/block.
// ---------------------------------------------------------------------------
__global__ void __launch_bounds__(256)
kgather(const int* __restrict__ x, const int* __restrict__ y,
        const float* __restrict__ cemb, const float* __restrict__ wemb,
        float* __restrict__ out) {
  const int tid = threadIdx.x;
  const int row0 = blockIdx.x * 128;
  int row = tid >> 1, half = tid & 1;
  int gb = row0 + row;
  int xi = x[gb * 2 + half];
  const float4* s4 = reinterpret_cast<const float4*>(cemb + (size_t)xi * 64);
  float4* d4 = reinterpret_cast<float4*>(&g_ctxp[(size_t)gb * K_ + half * 64]);
#pragma unroll
  for (int q = 0; q < 16; q++) d4[q] = s4[q];
  int yy = y[gb];
  const float4* w4 = reinterpret_cast<const float4*>(wemb + (size_t)yy * 64 + half * 32);
  float4* o4 = reinterpret_cast<float4*>(&out[(size_t)B_ * 64 + (size_t)gb * 64 + half * 32]);
#pragma unroll
  for (int q = 0; q < 8; q++) o4[q] = w4[q];
  if (tid < 128) g_best[row0 + tid] = ~0ull;
}

// ---------------------------------------------------------------------------
// Kz: 64-row chunks, 2 blocks/SM; z = ctx @ Wz'[a] + c2'[a]; reward; argmin.
// Warp tile 32 rows x 16 cols; 2 column passes cover h=0..127.
// ---------------------------------------------------------------------------
__global__ void __launch_bounds__(256, 2)
kz(const float* __restrict__ Wr2) {
  extern __shared__ float smf[];
  u64* wzs = reinterpret_cast<u64*>(smf + ZF_WZ);
  float* red = smf + ZF_RED;
  const uint32_t smb = smem_u32(smf);
  const int tid = threadIdx.x;
  const int row0 = blockIdx.x * 64;
  const int grp = blockIdx.y;
  const int wid = tid >> 5, lane = tid & 31;
  const int R0 = (wid >> 2) * 32, Cq = (wid & 3) * 16, cqi = wid & 3;
  const int rg = lane >> 2, cg = lane & 3;

  float2 wr2v[2][2];
#pragma unroll
  for (int p = 0; p < 2; p++)
#pragma unroll
    for (int j = 0; j < 2; j++)
      wr2v[p][j] = *reinterpret_cast<const float2*>(&Wr2[p * 64 + Cq + 8 * j + 2 * cg]);

  // stage ctx + wz(a0)
  {
    const float* src = g_ctxp + (size_t)row0 * K_;
    for (int it = 0; it < 8; it++) {
      int idx = tid + it * 256;
      int row = idx >> 5, q = idx & 31;
      cp16(smb + (ZF_CTX + row * CTXS + q * 4) * 4, src + row * K_ + q * 4);
    }
    const u64* wsrc = g_wz + (size_t)(grp * 4) * 8192;
    for (int it = 0; it < 16; it++) {
      int idx = tid + it * 256;
      cp16(smb + ZF_WZ * 4 + idx * 16, wsrc + idx * 2);
    }
    cp_commit(); cp_wait0();
  }
  __syncthreads();

#pragma unroll 1
  for (int ai = 0; ai < 4; ai++) {
    const int a = grp * 4 + ai;
    float s[4] = {0.f, 0.f, 0.f, 0.f};

#pragma unroll 1
    for (int p = 0; p < 2; p++) {
      const int Cb = p * 64 + Cq;
      float2 cc[2];
#pragma unroll
      for (int j = 0; j < 2; j++)
        cc[j] = *reinterpret_cast<const float2*>(&g_c2[a * H_ + Cb + 8 * j + 2 * cg]);

      u64 acc[4][2][2];
#pragma unroll
      for (int i = 0; i < 4; i++)
#pragma unroll
        for (int j = 0; j < 2; j++) { acc[i][j][0] = 0ull; acc[i][j][1] = 0ull; }

      const float* xb = smf + ZF_CTX + (R0 + rg) * CTXS;
      const u64*   wb = wzs + Cb + 2 * cg;
#pragma unroll 8
      for (int kq = 0; kq < 32; kq++) {
        ulonglong2 xv[4];
#pragma unroll
        for (int i = 0; i < 4; i++)
          xv[i] = *reinterpret_cast<const ulonglong2*>(xb + i * 8 * CTXS + kq * 4);
        ulonglong2 w0[2], w1[2];
#pragma unroll
        for (int j = 0; j < 2; j++) {
          w0[j] = *reinterpret_cast<const ulonglong2*>(wb + (2 * kq + 0) * H_ + 8 * j);
          w1[j] = *reinterpret_cast<const ulonglong2*>(wb + (2 * kq + 1) * H_ + 8 * j);
        }
#pragma unroll
        for (int i = 0; i < 4; i++)
#pragma unroll
          for (int j = 0; j < 2; j++) {
            ffma2(acc[i][j][0], xv[i].x, w0[j].x);
            ffma2(acc[i][j][1], xv[i].x, w0[j].y);
            ffma2(acc[i][j][0], xv[i].y, w1[j].x);
            ffma2(acc[i][j][1], xv[i].y, w1[j].y);
          }
      }

#pragma unroll
      for (int i = 0; i < 4; i++)
#pragma unroll
        for (int j = 0; j < 2; j++) {
          float e0, o0, e1, o1;
          unpack2(acc[i][j][0], e0, o0);
          unpack2(acc[i][j][1], e1, o1);
          float z0 = e0 + o0 + cc[j].x;
          float z1 = e1 + o1 + cc[j].y;
          s[i] = fmaf(fmaxf(z0, 0.f), wr2v[p][j].x, s[i]);
          s[i] = fmaf(fmaxf(z1, 0.f), wr2v[p][j].y, s[i]);
        }
    }

    // reduce over cg lanes
#pragma unroll
    for (int i = 0; i < 4; i++) {
      s[i] += __shfl_xor_sync(0xffffffffu, s[i], 1);
      s[i] += __shfl_xor_sync(0xffffffffu, s[i], 2);
    }
    if (cg == 0) {
#pragma unroll
      for (int i = 0; i < 4; i++)
        red[(R0 + rg + 8 * i) * 4 + cqi] = s[i];
    }
    __syncthreads();   // gemm reads of wz done; red visible

    if (ai < 3) {      // overlap next-wz staging with argmin
      const u64* src = g_wz + (size_t)(a + 1) * 8192;
      for (int it = 0; it < 16; it++) {
        int idx = tid + it * 256;
        cp16(smb + ZF_WZ * 4 + idx * 16, src + idx * 2);
      }
      cp_commit();
    }
    if (tid < 64) {
      float tot = red[tid * 4] + red[tid * 4 + 1] + red[tid * 4 + 2] + red[tid * 4 + 3];
      u64 key = ((u64)fkey(tot) << 32) | (unsigned)a;
      atomicMin(&g_best[row0 + tid], key);   // ties -> smaller a = first-min
    }
    if (ai < 3) cp_wait0();
    __syncthreads();
  }
}

// ---------------------------------------------------------------------------
// K2b: bucket rows by winning action.
// ---------------------------------------------------------------------------
__global__ void __launch_bounds__(256)
k2b_bucket() {
  int b = blockIdx.x * 256 + threadIdx.x;
  if (b < B_) {
    u64 v = g_best[b];
    int a = (int)(v & 0xFFu);
    int slot = atomicAdd(&g_bcnt[a], 1);
    g_bucket[a * B_ + slot] = b;
  }
}

// ---------------------------------------------------------------------------
// K3: winner preds (exact fp32), bucketed by action (64 chunks per action).
// ---------------------------------------------------------------------------
__global__ void __launch_bounds__(256)
k3_preds(const int* __restrict__ x, const float* __restrict__ cemb,
         float* __restrict__ out) {
  __shared__ float weffs[K_ * D_];
  __shared__ float ctxb[8][K_];
  const int a = blockIdx.x >> 6;
  const int chunk = blockIdx.x & 63;
  const int tid = threadIdx.x, wid = tid >> 5, lid = tid & 31;

  for (int i = tid; i < K_ * D_ / 4; i += 256)
    reinterpret_cast<float4*>(weffs)[i] =
        reinterpret_cast<const float4*>(g_weff + (size_t)a * K_ * D_)[i];
  __syncthreads();

  const int cnt = g_bcnt[a];
  const float bf0 = g_beff[a * D_ + 2 * lid];
  const float bf1 = g_beff[a * D_ + 2 * lid + 1];

  for (int ii = wid;; ii += 8) {
    int i = chunk + 64 * ii;
    if (i >= cnt) break;
    int b = g_bucket[a * B_ + i];
    {
      int k0 = lid * 4;
      int xi = x[2 * b + (lid >> 4)];
      float4 v = *reinterpret_cast<const float4*>(cemb + (size_t)xi * 64 + (k0 & 63));
      *reinterpret_cast<float4*>(&ctxb[wid][k0]) = v;
    }
    __syncwarp();
    float s0 = bf0, s1 = bf1;
#pragma unroll 4
    for (int k = 0; k < K_; k++) {
      float c = ctxb[wid][k];
      s0 = fmaf(c, weffs[k * D_ + 2 * lid], s0);
      s1 = fmaf(c, weffs[k * D_ + 2 * lid + 1], s1);
    }
    *reinterpret_cast<float2*>(&out[(size_t)b * 64 + 2 * lid]) = make_float2(s0, s1);
    __syncwarp();
  }
}

extern "C" void kernel_launch(void* const* d_in, const int* in_sizes, int n_in,
                              void* d_out, int out_size) {
  (void)in_sizes; (void)n_in; (void)out_size;
  const int*   x    = (const int*)d_in[0];
  const int*   y    = (const int*)d_in[1];
  const float* cemb = (const float*)d_in[2];
  const float* wemb = (const float*)d_in[3];
  const float* W1   = (const float*)d_in[4];
  const float* b1   = (const float*)d_in[5];
  const float* W2   = (const float*)d_in[6];
  const float* b2   = (const float*)d_in[7];
  const float* Wr1  = (const float*)d_in[8];
  const float* br1  = (const float*)d_in[9];
  const float* Wr2  = (const float*)d_in[10];
  float* out = (float*)d_out;

  cudaFuncSetAttribute(kz, cudaFuncAttributeMaxDynamicSharedMemorySize, ZSMEM);

  k1a_weff<<<A_, 256>>>(W1, b1, W2, b2);
  k1b_wz<<<A_, 256>>>(Wr1, br1);
  kgather<<<B_ / 128, 256>>>(x, y, cemb, wemb, out);
  kz<<<dim3(ZCH, GRP), 256, ZSMEM>>>(Wr2);
  k2b_bucket<<<B_ / 256, 256>>>();
  k3_preds<<<A_ * 64, 256>>>(x, cemb, out);
}

// round 15
// speedup vs baseline: 1.1645x; 1.0636x over previous
#include <cuda_runtime.h>
#include <cstdint>

namespace {

constexpr int B_ = 32768, A_ = 32, D_ = 64, H_ = 128, K_ = 128;
constexpr int ZCH = 512;     // 64-row chunks (kz)
constexpr int GRP = 8;       // action groups of 4

using u64 = unsigned long long;

// kz smem (floats)
constexpr int CTXS   = 132;          // padded ctx row stride (floats)
constexpr int ZF_CTX = 0;            // 64*132 = 8448 f
constexpr int ZF_WZ  = 8448;         // u64[8192] = 16384 f
constexpr int ZF_RED = 24832;        // 128 f
constexpr int ZSMEM  = 24960 * 4;    // 99840 B  (2 blocks/SM)

__device__ __forceinline__ void ffma2(u64& d, u64 a, u64 b) {
  asm("fma.rn.f32x2 %0, %1, %2, %0;" : "+l"(d) : "l"(a), "l"(b));
}
__device__ __forceinline__ u64 pack2(float a, float b) {
  u64 r; asm("mov.b64 %0, {%1, %2};" : "=l"(r) : "f"(a), "f"(b)); return r;
}
__device__ __forceinline__ void unpack2(u64 v, float& lo, float& hi) {
  asm("mov.b64 {%0, %1}, %2;" : "=f"(lo), "=f"(hi) : "l"(v));
}
__device__ __forceinline__ uint32_t fkey(float f) {
  uint32_t u = __float_as_uint(f);
  return (u & 0x80000000u) ? ~u : (u | 0x80000000u);
}
__device__ __forceinline__ uint32_t smem_u32(const void* p) {
  uint32_t a;
  asm("{ .reg .u64 t; cvta.to.shared.u64 t, %1; cvt.u32.u64 %0, t; }" : "=r"(a) : "l"(p));
  return a;
}
__device__ __forceinline__ void cp16(uint32_t dst, const void* src) {
  asm volatile("cp.async.cg.shared.global [%0], [%1], 16;" :: "r"(dst), "l"(src));
}
__device__ __forceinline__ void cp_commit() {
  asm volatile("cp.async.commit_group;" ::: "memory");
}
__device__ __forceinline__ void cp_wait0() {
  asm volatile("cp.async.wait_group 0;" ::: "memory");
}

}  // namespace

// -------- device scratch (no runtime alloc) --------
__device__ float g_weff[A_ * K_ * D_];                 // [a][k][d]
__device__ float g_beff[A_ * D_];                      // [a][d]
__device__ __align__(16) u64 g_wz[A_ * 64 * H_];       // [a][kp][h]; Wz+Wc folded
__device__ float g_c2[A_ * H_];                        // [a][h];    c2+br1 folded
__device__ __align__(16) float g_ctxp[(size_t)B_ * K_];
__device__ u64   g_best[B_];
__device__ int   g_bcnt[A_];
__device__ int   g_bucket[A_ * B_];

// ---------------------------------------------------------------------------
// K1a: Weff[a][k][d] = sum_h W2[a][d][h]*W1[a][h][k];  beff; bcnt reset
// ---------------------------------------------------------------------------
__global__ void __launch_bounds__(256)
k1a_weff(const float* __restrict__ W1, const float* __restrict__ b1,
         const float* __restrict__ W2, const float* __restrict__ b2) {
  __shared__ float w1s[H_][K_];
  __shared__ float w2s[D_][H_];
  const int a = blockIdx.x, tid = threadIdx.x;
  if (a == 0 && tid < A_) g_bcnt[tid] = 0;
  const float* W1a = W1 + (size_t)a * H_ * K_;
  const float* W2a = W2 + (size_t)a * D_ * H_;
  for (int i = tid; i < H_ * K_ / 4; i += 256)
    reinterpret_cast<float4*>(&w1s[0][0])[i] = reinterpret_cast<const float4*>(W1a)[i];
  for (int i = tid; i < D_ * H_ / 4; i += 256)
    reinterpret_cast<float4*>(&w2s[0][0])[i] = reinterpret_cast<const float4*>(W2a)[i];
  __syncthreads();

  const int k0 = (tid & 31) * 4, d0 = (tid >> 5) * 8;
  float acc[4][8];
#pragma unroll
  for (int i = 0; i < 4; i++)
#pragma unroll
    for (int j = 0; j < 8; j++) acc[i][j] = 0.f;
  for (int h = 0; h < H_; h++) {
    float4 w1v = *reinterpret_cast<const float4*>(&w1s[h][k0]);
    float w1x[4] = {w1v.x, w1v.y, w1v.z, w1v.w};
#pragma unroll
    for (int j = 0; j < 8; j++) {
      float w2v = w2s[d0 + j][h];
#pragma unroll
      for (int i = 0; i < 4; i++) acc[i][j] = fmaf(w2v, w1x[i], acc[i][j]);
    }
  }
  float* dst = g_weff + (size_t)a * K_ * D_;
#pragma unroll
  for (int i = 0; i < 4; i++)
#pragma unroll
    for (int j = 0; j < 8; j++) dst[(k0 + i) * D_ + d0 + j] = acc[i][j];

  if (tid < D_) {
    float s = b2[a * D_ + tid];
    for (int h = 0; h < H_; h++) s = fmaf(w2s[tid][h], b1[a * H_ + h], s);
    g_beff[a * D_ + tid] = s;
  }
}

// ---------------------------------------------------------------------------
// K1b: Wz'[a][kp][h] = pack over k of ( Wc[h][k] + sum_d Weff[a][k][d]*Wp[h][d] )
//      c2'[a][h]     = br1[h] + sum_d beff[a][d]*Wp[h][d]
// ---------------------------------------------------------------------------
__global__ void __launch_bounds__(256)
k1b_wz(const float* __restrict__ Wr1, const float* __restrict__ br1) {
  __shared__ float weffs[K_ * D_];
  __shared__ float wps[H_ * 65];
  const int a = blockIdx.x, tid = threadIdx.x;

  for (int i = tid; i < K_ * D_ / 4; i += 256)
    reinterpret_cast<float4*>(weffs)[i] =
        reinterpret_cast<const float4*>(g_weff + (size_t)a * K_ * D_)[i];
  for (int i = tid; i < H_ * D_ / 4; i += 256) {
    int n = i >> 4, q = i & 15;
    float4 v = *reinterpret_cast<const float4*>(&Wr1[n * 192 + 128 + q * 4]);
    wps[n * 65 + q * 4 + 0] = v.x;
    wps[n * 65 + q * 4 + 1] = v.y;
    wps[n * 65 + q * 4 + 2] = v.z;
    wps[n * 65 + q * 4 + 3] = v.w;
  }
  __syncthreads();

  const int h = tid & 127, khalf = tid >> 7;
  float prev = 0.f;
  for (int k = khalf * 64; k < khalf * 64 + 64; k++) {
    float s = Wr1[h * 192 + k];          // fold Wc
#pragma unroll 8
    for (int d = 0; d < D_; d++) s = fmaf(weffs[k * D_ + d], wps[h * 65 + d], s);
    if (k & 1)
      g_wz[(size_t)a * 8192 + (k >> 1) * H_ + h] = pack2(prev, s);
    else
      prev = s;
  }
  if (tid < H_) {
    float s = br1[tid];                  // fold br1
    for (int d = 0; d < D_; d++) s = fmaf(g_beff[a * D_ + d], wps[tid * 65 + d], s);
    g_c2[a * H_ + tid] = s;
  }
}

// ---------------------------------------------------------------------------
// Kgather: ctx -> g_ctxp (packed); wemb copy; g_best init.  128 rows/block.
// ---------------------------------------------------------------------------
__global__ void __launch_bounds__(256)
kgather(const int* __restrict__ x, const int* __restrict__ y,
        const float* __restrict__ cemb, const float* __restrict__ wemb,
        float* __restrict__ out) {
  const int tid = threadIdx.x;
  const int row0 = blockIdx.x * 128;
  int row = tid >> 1, half = tid & 1;
  int gb = row0 + row;
  int xi = x[gb * 2 + half];
  const float4* s4 = reinterpret_cast<const float4*>(cemb + (size_t)xi * 64);
  float4* d4 = reinterpret_cast<float4*>(&g_ctxp[(size_t)gb * K_ + half * 64]);
#pragma unroll
  for (int q = 0; q < 16; q++) d4[q] = s4[q];
  int yy = y[gb];
  const float4* w4 = reinterpret_cast<const float4*>(wemb + (size_t)yy * 64 + half * 32);
  float4* o4 = reinterpret_cast<float4*>(&out[(size_t)B_ * 64 + (size_t)gb * 64 + half * 32]);
#pragma unroll
  for (int q = 0; q < 8; q++) o4[q] = w4[q];
  if (tid < 128) g_best[row0 + tid] = ~0ull;
}

// ---------------------------------------------------------------------------
// Kz: 64-row chunks, 2 blocks/SM; z = ctx @ Wz'[a] + c2'[a]; reward; argmin.
// Warp tile 16 rows x 64 cols (4 row stripes x 2 col stripes);
// lane = rg*8+cg: thread = 4 rows (rg+4i) x 8 cols (16j+2cg+e).
// Weight LDS phases are full 128B (8 distinct addrs, bank stride 4).
// ---------------------------------------------------------------------------
__global__ void __launch_bounds__(256, 2)
kz(const float* __restrict__ Wr2) {
  extern __shared__ float smf[];
  u64* wzs = reinterpret_cast<u64*>(smf + ZF_WZ);
  float* red = smf + ZF_RED;
  const uint32_t smb = smem_u32(smf);
  const int tid = threadIdx.x;
  const int row0 = blockIdx.x * 64;
  const int grp = blockIdx.y;
  const int wid = tid >> 5, lane = tid & 31;
  const int R0 = (wid >> 1) * 16;        // 4 row stripes
  const int Cs = wid & 1, C0 = Cs * 64;  // 2 col stripes
  const int rg = lane >> 3, cg = lane & 7;

  float2 wr2v[4];
#pragma unroll
  for (int j = 0; j < 4; j++)
    wr2v[j] = *reinterpret_cast<const float2*>(&Wr2[C0 + 16 * j + 2 * cg]);

  // stage ctx + wz(a0)
  {
    const float* src = g_ctxp + (size_t)row0 * K_;
    for (int it = 0; it < 8; it++) {
      int idx = tid + it * 256;
      int row = idx >> 5, q = idx & 31;
      cp16(smb + (ZF_CTX + row * CTXS + q * 4) * 4, src + row * K_ + q * 4);
    }
    const u64* wsrc = g_wz + (size_t)(grp * 4) * 8192;
    for (int it = 0; it < 16; it++) {
      int idx = tid + it * 256;
      cp16(smb + ZF_WZ * 4 + idx * 16, wsrc + idx * 2);
    }
    cp_commit(); cp_wait0();
  }
  __syncthreads();

#pragma unroll 1
  for (int ai = 0; ai < 4; ai++) {
    const int a = grp * 4 + ai;

    float2 cc[4];
#pragma unroll
    for (int j = 0; j < 4; j++)
      cc[j] = *reinterpret_cast<const float2*>(&g_c2[a * H_ + C0 + 16 * j + 2 * cg]);

    u64 acc[4][4][2];
#pragma unroll
    for (int i = 0; i < 4; i++)
#pragma unroll
      for (int j = 0; j < 4; j++) { acc[i][j][0] = 0ull; acc[i][j][1] = 0ull; }

    const float* xb = smf + ZF_CTX + (R0 + rg) * CTXS;
    const u64*   wb = wzs + C0 + 2 * cg;
#pragma unroll 4
    for (int kq = 0; kq < 32; kq++) {
      ulonglong2 xv[4];
#pragma unroll
      for (int i = 0; i < 4; i++)
        xv[i] = *reinterpret_cast<const ulonglong2*>(xb + i * 4 * CTXS + kq * 4);
      ulonglong2 w0[4], w1[4];
#pragma unroll
      for (int j = 0; j < 4; j++) {
        w0[j] = *reinterpret_cast<const ulonglong2*>(wb + (2 * kq + 0) * H_ + 16 * j);
        w1[j] = *reinterpret_cast<const ulonglong2*>(wb + (2 * kq + 1) * H_ + 16 * j);
      }
#pragma unroll
      for (int i = 0; i < 4; i++)
#pragma unroll
        for (int j = 0; j < 4; j++) {
          ffma2(acc[i][j][0], xv[i].x, w0[j].x);
          ffma2(acc[i][j][1], xv[i].x, w0[j].y);
          ffma2(acc[i][j][0], xv[i].y, w1[j].x);
          ffma2(acc[i][j][1], xv[i].y, w1[j].y);
        }
    }

    float s[4] = {0.f, 0.f, 0.f, 0.f};
#pragma unroll
    for (int i = 0; i < 4; i++)
#pragma unroll
      for (int j = 0; j < 4; j++) {
        float e0, o0, e1, o1;
        unpack2(acc[i][j][0], e0, o0);
        unpack2(acc[i][j][1], e1, o1);
        float z0 = e0 + o0 + cc[j].x;
        float z1 = e1 + o1 + cc[j].y;
        s[i] = fmaf(fmaxf(z0, 0.f), wr2v[j].x, s[i]);
        s[i] = fmaf(fmaxf(z1, 0.f), wr2v[j].y, s[i]);
      }

    // reduce over the 8 cg lanes (lane bits 0-2)
#pragma unroll
    for (int i = 0; i < 4; i++) {
      s[i] += __shfl_xor_sync(0xffffffffu, s[i], 1);
      s[i] += __shfl_xor_sync(0xffffffffu, s[i], 2);
      s[i] += __shfl_xor_sync(0xffffffffu, s[i], 4);
    }
    if (cg == 0) {
#pragma unroll
      for (int i = 0; i < 4; i++)
        red[(R0 + rg + 4 * i) * 2 + Cs] = s[i];
    }
    __syncthreads();   // gemm reads of wz done; red visible

    if (ai < 3) {      // overlap next-wz staging with argmin
      const u64* src = g_wz + (size_t)(a + 1) * 8192;
      for (int it = 0; it < 16; it++) {
        int idx = tid + it * 256;
        cp16(smb + ZF_WZ * 4 + idx * 16, src + idx * 2);
      }
      cp_commit();
    }
    if (tid < 64) {
      float tot = red[tid * 2] + red[tid * 2 + 1];
      u64 key = ((u64)fkey(tot) << 32) | (unsigned)a;
      atomicMin(&g_best[row0 + tid], key);   // ties -> smaller a = first-min
    }
    if (ai < 3) cp_wait0();
    __syncthreads();
  }
}

// ---------------------------------------------------------------------------
// K2b: bucket rows by winning action.
// ---------------------------------------------------------------------------
__global__ void __launch_bounds__(256)
k2b_bucket() {
  int b = blockIdx.x * 256 + threadIdx.x;
  if (b < B_) {
    u64 v = g_best[b];
    int a = (int)(v & 0xFFu);
    int slot = atomicAdd(&g_bcnt[a], 1);
    g_bucket[a * B_ + slot] = b;
  }
}

// ---------------------------------------------------------------------------
// K3: winner preds (exact fp32), bucketed by action (64 chunks per action).
// ---------------------------------------------------------------------------
__global__ void __launch_bounds__(256)
k3_preds(const int* __restrict__ x, const float* __restrict__ cemb,
         float* __restrict__ out) {
  __shared__ float weffs[K_ * D_];
  __shared__ float ctxb[8][K_];
  const int a = blockIdx.x >> 6;
  const int chunk = blockIdx.x & 63;
  const int tid = threadIdx.x, wid = tid >> 5, lid = tid & 31;

  for (int i = tid; i < K_ * D_ / 4; i += 256)
    reinterpret_cast<float4*>(weffs)[i] =
        reinterpret_cast<const float4*>(g_weff + (size_t)a * K_ * D_)[i];
  __syncthreads();

  const int cnt = g_bcnt[a];
  const float bf0 = g_beff[a * D_ + 2 * lid];
  const float bf1 = g_beff[a * D_ + 2 * lid + 1];

  for (int ii = wid;; ii += 8) {
    int i = chunk + 64 * ii;
    if (i >= cnt) break;
    int b = g_bucket[a * B_ + i];
    {
      int k0 = lid * 4;
      int xi = x[2 * b + (lid >> 4)];
      float4 v = *reinterpret_cast<const float4*>(cemb + (size_t)xi * 64 + (k0 & 63));
      *reinterpret_cast<float4*>(&ctxb[wid][k0]) = v;
    }
    __syncwarp();
    float s0 = bf0, s1 = bf1;
#pragma unroll 4
    for (int k = 0; k < K_; k++) {
      float c = ctxb[wid][k];
      s0 = fmaf(c, weffs[k * D_ + 2 * lid], s0);
      s1 = fmaf(c, weffs[k * D_ + 2 * lid + 1], s1);
    }
    *reinterpret_cast<float2*>(&out[(size_t)b * 64 + 2 * lid]) = make_float2(s0, s1);
    __syncwarp();
  }
}

extern "C" void kernel_launch(void* const* d_in, const int* in_sizes, int n_in,
                              void* d_out, int out_size) {
  (void)in_sizes; (void)n_in; (void)out_size;
  const int*   x    = (const int*)d_in[0];
  const int*   y    = (const int*)d_in[1];
  const float* cemb = (const float*)d_in[2];
  const float* wemb = (const float*)d_in[3];
  const float* W1   = (const float*)d_in[4];
  const float* b1   = (const float*)d_in[5];
  const float* W2   = (const float*)d_in[6];
  const float* b2   = (const float*)d_in[7];
  const float* Wr1  = (const float*)d_in[8];
  const float* br1  = (const float*)d_in[9];
  const float* Wr2  = (const float*)d_in[10];
  float* out = (float*)d_out;

  cudaFuncSetAttribute(kz, cudaFuncAttributeMaxDynamicSharedMemorySize, ZSMEM);

  k1a_weff<<<A_, 256>>>(W1, b1, W2, b2);
  k1b_wz<<<A_, 256>>>(Wr1, br1);
  kgather<<<B_ / 128, 256>>>(x, y, cemb, wemb, out);
  kz<<<dim3(ZCH, GRP), 256, ZSMEM>>>(Wr2);
  k2b_bucket<<<B_ / 256, 256>>>();
  k3_preds<<<A_ * 64, 256>>>(x, cemb, out);
}